// round 5
// baseline (speedup 1.0000x reference)
#include <cuda_runtime.h>
#include <cstdint>
#include <cstddef>

#define N_NODE 50000
#define N_EDGE 625000
#define FD 128
#define EPS 1e-5f
#define TM 64

// ---------------------------------------------------------------------------
// Device scratch (no allocs allowed)
// ---------------------------------------------------------------------------
__device__ float g_agg[(size_t)N_NODE * FD];
__device__ float g_Wt1[128 * 256];  // Wt1[n][k] = tf32(W1[k][n])
__device__ float g_Wt2[128 * 128];
__device__ float g_Wt3[128 * 128];

__device__ __forceinline__ float to_tf32(float x) {
    uint32_t r;
    asm("cvt.rna.tf32.f32 %0, %1;" : "=r"(r) : "f"(x));
    return __uint_as_float(r);
}
__device__ __forceinline__ uint32_t smem_u32(const void* p) {
    uint32_t a;
    asm("{ .reg .u64 t; cvta.to.shared.u64 t, %1; cvt.u32.u64 %0, t; }"
        : "=r"(a) : "l"(p));
    return a;
}
__device__ __forceinline__ void ldsm4(uint32_t a[4], uint32_t addr) {
    asm volatile("ldmatrix.sync.aligned.m8n8.x4.shared.b16 {%0,%1,%2,%3}, [%4];"
                 : "=r"(a[0]), "=r"(a[1]), "=r"(a[2]), "=r"(a[3]) : "r"(addr));
}

#define MMA_TF32(c, a0, a1, a2, a3, b0, b1)                                       \
    asm volatile("mma.sync.aligned.m16n8k8.row.col.f32.tf32.tf32.f32 "            \
                 "{%0,%1,%2,%3}, {%4,%5,%6,%7}, {%8,%9}, {%0,%1,%2,%3};"          \
                 : "+f"((c)[0]), "+f"((c)[1]), "+f"((c)[2]), "+f"((c)[3])         \
                 : "r"(a0), "r"(a1), "r"(a2), "r"(a3), "r"(b0), "r"(b1))

// ---------------------------------------------------------------------------
// Kernel: scatter-add edge features (warp/edge, red.global.add.v4)
// ---------------------------------------------------------------------------
__global__ void scatter_edges_kernel(const int* __restrict__ em,
                                     const float* __restrict__ ef) {
    int e = blockIdx.x * 8 + (threadIdx.x >> 5);
    if (e >= N_EDGE) return;
    int lane = threadIdx.x & 31;
    int r = em[N_EDGE + e];
    float4 v = *(const float4*)(ef + (size_t)e * FD + lane * 4);
    float* dst = g_agg + (size_t)r * FD + lane * 4;
    asm volatile("red.global.add.v4.f32 [%0], {%1,%2,%3,%4};"
                 :: "l"(dst), "f"(v.x), "f"(v.y), "f"(v.z), "f"(v.w) : "memory");
}

// ---------------------------------------------------------------------------
// Kernel: transpose + tf32-round weights into n-major device globals
// ---------------------------------------------------------------------------
__global__ void prep_weights_kernel(const float* __restrict__ W1,
                                    const float* __restrict__ W2,
                                    const float* __restrict__ W3) {
    int i = blockIdx.x * blockDim.x + threadIdx.x;
    if (i < 256 * 128) {
        int k = i >> 7, n = i & 127;
        g_Wt1[n * 256 + k] = to_tf32(W1[i]);
    } else if (i < 256 * 128 + 128 * 128) {
        int j = i - 256 * 128;
        int k = j >> 7, n = j & 127;
        g_Wt2[n * 128 + k] = to_tf32(W2[j]);
    } else if (i < 256 * 128 + 2 * 128 * 128) {
        int j = i - 256 * 128 - 128 * 128;
        int k = j >> 7, n = j & 127;
        g_Wt3[n * 128 + k] = to_tf32(W3[j]);
    }
}

// ---------------------------------------------------------------------------
// Fused MLP + LN + residual. TM=64 rows/CTA, 256 threads (8 warps =
// 4 row-strips x 2 col-halves, warp tile 16x64). k=16 chunk ping-pong
// staging with register prefetch; ONE barrier per chunk. 3 CTAs/SM.
// Strides: hs 132 (==4 mod 32), stage 20 (==20 mod 32) -> ldmatrix
// phases conflict-free (verified: 8 row starts mod 32 all distinct).
// ---------------------------------------------------------------------------
#define HST 132
#define SST 20
#define OFF_HS   0
#define OFF_WS0  8448            // 64*132
#define OFF_WS1  11008           // +128*20
#define OFF_XS0  13568
#define OFF_XS1  14848           // +64*20
#define OFF_BIAS 16128
#define OFF_LN   16768           // [64][4]
#define SMEM_FL  17024
#define SMEM_BYTES (SMEM_FL * 4)

__global__ void __launch_bounds__(256, 3)
mlp_mma_kernel(const float* __restrict__ nf,
               const float* __restrict__ b1, const float* __restrict__ b2,
               const float* __restrict__ b3, const float* __restrict__ gamma_p,
               const float* __restrict__ beta_p, float* __restrict__ out) {
    extern __shared__ float smem[];
    float* hs    = smem + OFF_HS;
    float* sBias = smem + OFF_BIAS;
    float* lnred = smem + OFF_LN;

    const int tid = threadIdx.x;
    const int wid = tid >> 5;
    const int lid = tid & 31;
    const int grp = lid >> 2;
    const int tig = lid & 3;
    const int wr = wid & 3;      // row strip
    const int wc = wid >> 2;     // col half
    const int r0 = wr * 16 + grp;
    const int base = blockIdx.x * TM;

    if (tid < 128) {
        sBias[tid]       = b1[tid];
        sBias[128 + tid] = b2[tid];
        sBias[256 + tid] = b3[tid];
        sBias[384 + tid] = gamma_p[tid];
        sBias[512 + tid] = beta_p[tid];
    }

    // ldmatrix lane patterns
    const int a_row = (lid & 7) + ((lid >> 3) & 1) * 8;
    const int a_col = (lid >> 4) * 4;
    const int b_row = (lid & 7) + (lid >> 4) * 8;
    const int b_col = ((lid >> 3) & 1) * 4;

    const uint32_t sb = smem_u32(smem);
    const uint32_t aXb = sb + (uint32_t)((OFF_XS0 + (wr * 16 + a_row) * SST + a_col) * 4);
    const uint32_t aHb = sb + (uint32_t)((OFF_HS + (wr * 16 + a_row) * HST + a_col) * 4);
    const uint32_t bWb = sb + (uint32_t)((OFF_WS0 + (wc * 64 + b_row) * SST + b_col) * 4);

    // staging indices
    const int s_row = tid >> 2;   // 0..63
    const int s_q = tid & 3;      // 0..3 (k-quad)
    float* xsST0 = smem + OFF_XS0 + s_row * SST + s_q * 4;
    float* wsST0 = smem + OFF_WS0 + s_row * SST + s_q * 4;           // n = s_row
    float* wsST1 = smem + OFF_WS0 + (s_row + 64) * SST + s_q * 4;    // n = s_row+64
    const int node_s = base + s_row;

    float acc[8][4];
#pragma unroll
    for (int nt = 0; nt < 8; ++nt)
#pragma unroll
        for (int j = 0; j < 4; ++j) acc[nt][j] = 0.f;

    float4 xr, w0, w1;

    // --------- Layer 1: X[64x256] @ Wt1, 16 chunks of k=16 ---------
#define LOADX(kt) do {                                                            \
        int gk = (kt) * 16 + s_q * 4;                                             \
        xr = make_float4(0.f, 0.f, 0.f, 0.f);                                     \
        if (node_s < N_NODE)                                                      \
            xr = (gk < FD) ? *(const float4*)(nf + (size_t)node_s * FD + gk)      \
                           : *(const float4*)(g_agg + (size_t)node_s * FD + gk - FD); \
    } while (0)
#define LOADW(Wt, ldw, kt) do {                                                   \
        w0 = *(const float4*)((Wt) + (size_t)s_row * (ldw) + (kt) * 16 + s_q * 4);\
        w1 = *(const float4*)((Wt) + (size_t)(s_row + 64) * (ldw) + (kt) * 16 + s_q * 4); \
    } while (0)
#define STSX(b) do {                                                              \
        float4 t;                                                                 \
        t.x = to_tf32(xr.x); t.y = to_tf32(xr.y);                                 \
        t.z = to_tf32(xr.z); t.w = to_tf32(xr.w);                                 \
        *(float4*)(xsST0 + (b) * (OFF_XS1 - OFF_XS0)) = t;                        \
    } while (0)
#define STSW(b) do {                                                              \
        *(float4*)(wsST0 + (b) * (OFF_WS1 - OFF_WS0)) = w0;                       \
        *(float4*)(wsST1 + (b) * (OFF_WS1 - OFF_WS0)) = w1;                       \
    } while (0)
#define MMA_CHUNK(abase)                                                          \
    _Pragma("unroll")                                                             \
    for (int ks = 0; ks < 2; ++ks) {                                              \
        uint32_t a[4];                                                            \
        ldsm4(a, (abase) + ks * 32);                                              \
        _Pragma("unroll")                                                         \
        for (int g = 0; g < 4; ++g) {                                             \
            uint32_t bf[4];                                                       \
            ldsm4(bf, bWb + bofs + g * 1280 + ks * 32);                           \
            MMA_TF32(acc[g * 2],     a[0], a[1], a[2], a[3], bf[0], bf[1]);       \
            MMA_TF32(acc[g * 2 + 1], a[0], a[1], a[2], a[3], bf[2], bf[3]);       \
        }                                                                         \
    }

    LOADX(0); LOADW(g_Wt1, 256, 0);
    STSX(0); STSW(0);
    __syncthreads();
    for (int kt = 0; kt < 16; ++kt) {
        int b = kt & 1;
        if (kt < 15) { LOADX(kt + 1); LOADW(g_Wt1, 256, kt + 1); }
        uint32_t bofs = (uint32_t)(b * (OFF_WS1 - OFF_WS0) * 4);
        MMA_CHUNK(aXb + (uint32_t)(b * (OFF_XS1 - OFF_XS0) * 4));
        if (kt < 15) { STSX(1 - b); STSW(1 - b); }
        __syncthreads();
    }

    // epilogue 1: bias+relu -> tf32 -> hs
#pragma unroll
    for (int nt = 0; nt < 8; ++nt) {
        int col = wc * 64 + nt * 8 + tig * 2;
        float2 v0, v1;
        v0.x = to_tf32(fmaxf(acc[nt][0] + sBias[col], 0.f));
        v0.y = to_tf32(fmaxf(acc[nt][1] + sBias[col + 1], 0.f));
        v1.x = to_tf32(fmaxf(acc[nt][2] + sBias[col], 0.f));
        v1.y = to_tf32(fmaxf(acc[nt][3] + sBias[col + 1], 0.f));
        *(float2*)(hs + r0 * HST + col) = v0;
        *(float2*)(hs + (r0 + 8) * HST + col) = v1;
    }

    // --------- Layers 2 & 3: H[64x128] @ Wt, 8 chunks of k=16 ---------
    for (int l = 0; l < 2; ++l) {
        const float* Wt = l ? g_Wt3 : g_Wt2;
#pragma unroll
        for (int nt = 0; nt < 8; ++nt)
#pragma unroll
            for (int j = 0; j < 4; ++j) acc[nt][j] = 0.f;

        LOADW(Wt, 128, 0);
        STSW(0);
        __syncthreads();   // covers hs writes (epi) + ws chunk0
        for (int kt = 0; kt < 8; ++kt) {
            int b = kt & 1;
            if (kt < 7) LOADW(Wt, 128, kt + 1);
            uint32_t bofs = (uint32_t)(b * (OFF_WS1 - OFF_WS0) * 4);
            MMA_CHUNK(aHb + (uint32_t)((kt * 16) * 4));
            if (kt < 7) STSW(1 - b);
            __syncthreads();
        }

        if (l == 0) {
#pragma unroll
            for (int nt = 0; nt < 8; ++nt) {
                int col = wc * 64 + nt * 8 + tig * 2;
                float2 v0, v1;
                v0.x = to_tf32(fmaxf(acc[nt][0] + sBias[128 + col], 0.f));
                v0.y = to_tf32(fmaxf(acc[nt][1] + sBias[128 + col + 1], 0.f));
                v1.x = to_tf32(fmaxf(acc[nt][2] + sBias[128 + col], 0.f));
                v1.y = to_tf32(fmaxf(acc[nt][3] + sBias[128 + col + 1], 0.f));
                *(float2*)(hs + r0 * HST + col) = v0;
                *(float2*)(hs + (r0 + 8) * HST + col) = v1;
            }
        }
    }

    // --------- Final: +b3, LayerNorm (cross-half via SMEM), residual ---------
    {
        float s0 = 0.f, sq0 = 0.f, s1 = 0.f, sq1 = 0.f;
#pragma unroll
        for (int nt = 0; nt < 8; ++nt) {
            int col = wc * 64 + nt * 8 + tig * 2;
            acc[nt][0] += sBias[256 + col];
            acc[nt][1] += sBias[256 + col + 1];
            acc[nt][2] += sBias[256 + col];
            acc[nt][3] += sBias[256 + col + 1];
            s0 += acc[nt][0] + acc[nt][1];
            sq0 += acc[nt][0] * acc[nt][0] + acc[nt][1] * acc[nt][1];
            s1 += acc[nt][2] + acc[nt][3];
            sq1 += acc[nt][2] * acc[nt][2] + acc[nt][3] * acc[nt][3];
        }
#pragma unroll
        for (int o = 1; o <= 2; o <<= 1) {
            s0 += __shfl_xor_sync(0xFFFFFFFFu, s0, o);
            sq0 += __shfl_xor_sync(0xFFFFFFFFu, sq0, o);
            s1 += __shfl_xor_sync(0xFFFFFFFFu, s1, o);
            sq1 += __shfl_xor_sync(0xFFFFFFFFu, sq1, o);
        }
        if (tig == 0) {
            lnred[r0 * 4 + wc * 2]           = s0;
            lnred[r0 * 4 + wc * 2 + 1]       = sq0;
            lnred[(r0 + 8) * 4 + wc * 2]     = s1;
            lnred[(r0 + 8) * 4 + wc * 2 + 1] = sq1;
        }
        __syncthreads();
        float st0 = lnred[r0 * 4] + lnred[r0 * 4 + 2];
        float qt0 = lnred[r0 * 4 + 1] + lnred[r0 * 4 + 3];
        float st1 = lnred[(r0 + 8) * 4] + lnred[(r0 + 8) * 4 + 2];
        float qt1 = lnred[(r0 + 8) * 4 + 1] + lnred[(r0 + 8) * 4 + 3];
        float mu0 = st0 * (1.f / 128.f);
        float ri0 = rsqrtf(qt0 * (1.f / 128.f) - mu0 * mu0 + EPS);
        float mu1 = st1 * (1.f / 128.f);
        float ri1 = rsqrtf(qt1 * (1.f / 128.f) - mu1 * mu1 + EPS);

        int node0 = base + r0;
        int node1 = base + r0 + 8;
#pragma unroll
        for (int nt = 0; nt < 8; ++nt) {
            int col = wc * 64 + nt * 8 + tig * 2;
            float g0 = sBias[384 + col], g1 = sBias[384 + col + 1];
            float be0 = sBias[512 + col], be1 = sBias[512 + col + 1];
            if (node0 < N_NODE) {
                float2 nv = *(const float2*)(nf + (size_t)node0 * FD + col);
                float2 o;
                o.x = (acc[nt][0] - mu0) * ri0 * g0 + be0 + nv.x;
                o.y = (acc[nt][1] - mu0) * ri0 * g1 + be1 + nv.y;
                *(float2*)(out + (size_t)node0 * FD + col) = o;
            }
            if (node1 < N_NODE) {
                float2 nv = *(const float2*)(nf + (size_t)node1 * FD + col);
                float2 o;
                o.x = (acc[nt][2] - mu1) * ri1 * g0 + be0 + nv.x;
                o.y = (acc[nt][3] - mu1) * ri1 * g1 + be1 + nv.y;
                *(float2*)(out + (size_t)node1 * FD + col) = o;
            }
        }
    }
}

// ---------------------------------------------------------------------------
extern "C" void kernel_launch(void* const* d_in, const int* in_sizes, int n_in,
                              void* d_out, int out_size) {
    const float* node_feature = (const float*)d_in[0];
    const int* edge_matrix    = (const int*)d_in[1];
    const float* edge_feature = (const float*)d_in[2];
    const float* W1 = (const float*)d_in[3];
    const float* b1 = (const float*)d_in[4];
    const float* W2 = (const float*)d_in[5];
    const float* b2 = (const float*)d_in[6];
    const float* W3 = (const float*)d_in[7];
    const float* b3 = (const float*)d_in[8];
    const float* gamma = (const float*)d_in[9];
    const float* beta  = (const float*)d_in[10];
    float* out = (float*)d_out;

    static void* agg_ptr = nullptr;
    static int inited = 0;
    if (!inited) {
        cudaGetSymbolAddress(&agg_ptr, g_agg);
        cudaFuncSetAttribute(mlp_mma_kernel,
                             cudaFuncAttributeMaxDynamicSharedMemorySize, SMEM_BYTES);
        inited = 1;
    }

    cudaMemsetAsync(agg_ptr, 0, (size_t)N_NODE * FD * sizeof(float));

    scatter_edges_kernel<<<(N_EDGE + 7) / 8, 256>>>(edge_matrix, edge_feature);

    prep_weights_kernel<<<(256 * 128 + 2 * 128 * 128 + 255) / 256, 256>>>(W1, W2, W3);

    int grid = (N_NODE + TM - 1) / TM;
    mlp_mma_kernel<<<grid, 256, SMEM_BYTES>>>(node_feature, b1, b2, b3,
                                              gamma, beta, out);
}

// round 6
// speedup vs baseline: 1.0025x; 1.0025x over previous
#include <cuda_runtime.h>
#include <cstdint>
#include <cstddef>

#define N_NODE 50000
#define N_EDGE 625000
#define FD 128
#define EPS 1e-5f
#define TM 128
#define NBLK 49   // ceil(50000/1024) scan blocks

// ---------------------------------------------------------------------------
// Device scratch (no allocs allowed)
// ---------------------------------------------------------------------------
__device__ float g_agg[(size_t)N_NODE * FD];
__device__ float g_Wt1[128 * 256];  // Wt1[n][k] = tf32(W1[k][n])
__device__ float g_Wt2[128 * 128];
__device__ float g_Wt3[128 * 128];
__device__ int g_cnt[N_NODE];       // per-node edge count (histogram)
__device__ int g_start[N_NODE];     // exclusive prefix (CSR row starts)
__device__ int g_cur[N_NODE];       // fill cursors
__device__ int g_btot[NBLK];        // scan block totals
__device__ int g_boff[NBLK];        // scan block offsets
__device__ int g_eidx[N_EDGE];      // edge ids grouped by receiver

__device__ __forceinline__ float to_tf32(float x) {
    uint32_t r;
    asm("cvt.rna.tf32.f32 %0, %1;" : "=r"(r) : "f"(x));
    return __uint_as_float(r);
}
__device__ __forceinline__ uint32_t smem_u32(const void* p) {
    uint32_t a;
    asm("{ .reg .u64 t; cvta.to.shared.u64 t, %1; cvt.u32.u64 %0, t; }"
        : "=r"(a) : "l"(p));
    return a;
}
__device__ __forceinline__ void ldsm4(uint32_t a[4], uint32_t addr) {
    asm volatile("ldmatrix.sync.aligned.m8n8.x4.shared.b16 {%0,%1,%2,%3}, [%4];"
                 : "=r"(a[0]), "=r"(a[1]), "=r"(a[2]), "=r"(a[3]) : "r"(addr));
}

#define MMA_TF32(c, a0, a1, a2, a3, b0, b1)                                       \
    asm volatile("mma.sync.aligned.m16n8k8.row.col.f32.tf32.tf32.f32 "            \
                 "{%0,%1,%2,%3}, {%4,%5,%6,%7}, {%8,%9}, {%0,%1,%2,%3};"          \
                 : "+f"((c)[0]), "+f"((c)[1]), "+f"((c)[2]), "+f"((c)[3])         \
                 : "r"(a0), "r"(a1), "r"(a2), "r"(a3), "r"(b0), "r"(b1))

// ---------------------------------------------------------------------------
// CSR build: histogram -> 3-phase scan -> fill
// ---------------------------------------------------------------------------
__global__ void hist_kernel(const int* __restrict__ em) {
    int e = blockIdx.x * blockDim.x + threadIdx.x;
    if (e < N_EDGE) atomicAdd(&g_cnt[em[N_EDGE + e]], 1);
}

__global__ void scan_a_kernel() {   // 49 blocks x 256 thr, 4 nodes/thr
    __shared__ int sh[256];
    int t = threadIdx.x;
    int base = blockIdx.x * 1024 + t * 4;
    int c0 = 0, c1 = 0, c2 = 0, c3 = 0;
    if (base < N_NODE)     c0 = g_cnt[base];
    if (base + 1 < N_NODE) c1 = g_cnt[base + 1];
    if (base + 2 < N_NODE) c2 = g_cnt[base + 2];
    if (base + 3 < N_NODE) c3 = g_cnt[base + 3];
    int s = c0 + c1 + c2 + c3;
    sh[t] = s;
    __syncthreads();
    for (int off = 1; off < 256; off <<= 1) {
        int v = (t >= off) ? sh[t - off] : 0;
        __syncthreads();
        sh[t] += v;
        __syncthreads();
    }
    int excl = sh[t] - s;
    if (base < N_NODE)     g_start[base] = excl;
    if (base + 1 < N_NODE) g_start[base + 1] = excl + c0;
    if (base + 2 < N_NODE) g_start[base + 2] = excl + c0 + c1;
    if (base + 3 < N_NODE) g_start[base + 3] = excl + c0 + c1 + c2;
    if (t == 255) g_btot[blockIdx.x] = sh[255];
}

__global__ void scan_b_kernel() {   // 1 thread: serial scan of 49 totals
    if (threadIdx.x == 0) {
        int run = 0;
        for (int i = 0; i < NBLK; ++i) { g_boff[i] = run; run += g_btot[i]; }
    }
}

__global__ void scan_c_kernel() {   // add block offsets, init cursors
    int i = blockIdx.x * blockDim.x + threadIdx.x;
    if (i < N_NODE) {
        int s = g_start[i] + g_boff[i >> 10];
        g_start[i] = s;
        g_cur[i] = s;
    }
}

__global__ void fill_kernel(const int* __restrict__ em) {
    int e = blockIdx.x * blockDim.x + threadIdx.x;
    if (e < N_EDGE) {
        int pos = atomicAdd(&g_cur[em[N_EDGE + e]], 1);
        g_eidx[pos] = e;
    }
}

// ---------------------------------------------------------------------------
// Gather: one warp per node, sum its edge rows (no atomics), write agg once.
// ---------------------------------------------------------------------------
__global__ void gather_kernel(const float* __restrict__ ef) {
    int node = blockIdx.x * 8 + (threadIdx.x >> 5);
    if (node >= N_NODE) return;
    int lane = threadIdx.x & 31;
    int start = g_start[node];
    int cnt = g_cnt[node];
    const float4* efv = (const float4*)ef;
    float4 a0 = make_float4(0.f, 0.f, 0.f, 0.f);
    float4 a1 = make_float4(0.f, 0.f, 0.f, 0.f);
    int i = 0;
    for (; i + 2 <= cnt; i += 2) {
        int e0 = g_eidx[start + i];
        int e1 = g_eidx[start + i + 1];
        float4 v0 = efv[(size_t)e0 * 32 + lane];
        float4 v1 = efv[(size_t)e1 * 32 + lane];
        a0.x += v0.x; a0.y += v0.y; a0.z += v0.z; a0.w += v0.w;
        a1.x += v1.x; a1.y += v1.y; a1.z += v1.z; a1.w += v1.w;
    }
    if (i < cnt) {
        int e0 = g_eidx[start + i];
        float4 v0 = efv[(size_t)e0 * 32 + lane];
        a0.x += v0.x; a0.y += v0.y; a0.z += v0.z; a0.w += v0.w;
    }
    a0.x += a1.x; a0.y += a1.y; a0.z += a1.z; a0.w += a1.w;
    ((float4*)g_agg)[(size_t)node * 32 + lane] = a0;
}

// ---------------------------------------------------------------------------
// Weight prep: transpose + tf32 round
// ---------------------------------------------------------------------------
__global__ void prep_weights_kernel(const float* __restrict__ W1,
                                    const float* __restrict__ W2,
                                    const float* __restrict__ W3) {
    int i = blockIdx.x * blockDim.x + threadIdx.x;
    if (i < 256 * 128) {
        int k = i >> 7, n = i & 127;
        g_Wt1[n * 256 + k] = to_tf32(W1[i]);
    } else if (i < 256 * 128 + 128 * 128) {
        int j = i - 256 * 128;
        int k = j >> 7, n = j & 127;
        g_Wt2[n * 128 + k] = to_tf32(W2[j]);
    } else if (i < 256 * 128 + 2 * 128 * 128) {
        int j = i - 256 * 128 - 128 * 128;
        int k = j >> 7, n = j & 127;
        g_Wt3[n * 128 + k] = to_tf32(W3[j]);
    }
}

// ---------------------------------------------------------------------------
// Fused tf32 mma.sync MLP + LN + residual (round-4 version: TM=128, 8 warps,
// warp tile 16x128, ldmatrix feed, strides 36/132 conflict-free).
// ---------------------------------------------------------------------------
#define XS_STRIDE 36
#define WS_STRIDE 36
#define HS_STRIDE 132
#define SMEM_FLOATS (128 * HS_STRIDE + 128 * WS_STRIDE + 128 * XS_STRIDE + 5 * 128)
#define SMEM_BYTES (SMEM_FLOATS * 4)

__global__ void __launch_bounds__(256, 2)
mlp_mma_kernel(const float* __restrict__ nf,
               const float* __restrict__ b1, const float* __restrict__ b2,
               const float* __restrict__ b3, const float* __restrict__ gamma_p,
               const float* __restrict__ beta_p, float* __restrict__ out) {
    extern __shared__ float smem[];
    float* hs = smem;
    float* ws = hs + 128 * HS_STRIDE;
    float* xs = ws + 128 * WS_STRIDE;
    float* sBias = xs + 128 * XS_STRIDE;

    const int tid = threadIdx.x;
    const int wid = tid >> 5;
    const int lid = tid & 31;
    const int grp = lid >> 2;
    const int tig = lid & 3;
    const int r0 = wid * 16 + grp;
    const int base = blockIdx.x * TM;

    if (tid < 128) {
        sBias[tid]       = b1[tid];
        sBias[128 + tid] = b2[tid];
        sBias[256 + tid] = b3[tid];
        sBias[384 + tid] = gamma_p[tid];
        sBias[512 + tid] = beta_p[tid];
    }

    const int a_row = (lid & 7) + ((lid >> 3) & 1) * 8;
    const int a_col = (lid >> 4) * 4;
    const int b_row = (lid & 7) + (lid >> 4) * 8;
    const int b_col = ((lid >> 3) & 1) * 4;

    const uint32_t aX = smem_u32(xs) + (uint32_t)(((wid * 16 + a_row) * XS_STRIDE + a_col) * 4);
    const uint32_t aH = smem_u32(hs) + (uint32_t)(((wid * 16 + a_row) * HS_STRIDE + a_col) * 4);
    const uint32_t bW = smem_u32(ws) + (uint32_t)((b_row * WS_STRIDE + b_col) * 4);

    float acc[16][4];
#pragma unroll
    for (int nt = 0; nt < 16; ++nt)
#pragma unroll
        for (int j = 0; j < 4; ++j) acc[nt][j] = 0.f;

    // Layer 1: X[128x256] @ W1
    for (int kt = 0; kt < 8; ++kt) {
#pragma unroll
        for (int it = 0; it < 4; ++it) {
            int i = tid + it * 256;
            int row = i >> 3, q = i & 7;
            int gk = kt * 32 + q * 4;
            float4 v = make_float4(0.f, 0.f, 0.f, 0.f);
            int node = base + row;
            if (node < N_NODE) {
                const float* src = (gk < FD)
                    ? nf + (size_t)node * FD + gk
                    : g_agg + (size_t)node * FD + (gk - FD);
                v = *(const float4*)src;
            }
            v.x = to_tf32(v.x); v.y = to_tf32(v.y);
            v.z = to_tf32(v.z); v.w = to_tf32(v.w);
            *(float4*)(xs + row * XS_STRIDE + q * 4) = v;
            float4 w = *(const float4*)(g_Wt1 + (size_t)row * 256 + gk);
            *(float4*)(ws + row * WS_STRIDE + q * 4) = w;
        }
        __syncthreads();
#pragma unroll
        for (int ks = 0; ks < 4; ++ks) {
            uint32_t a[4];
            ldsm4(a, aX + (uint32_t)(ks * 8 * 4));
#pragma unroll
            for (int nt2 = 0; nt2 < 8; ++nt2) {
                uint32_t b[4];
                ldsm4(b, bW + (uint32_t)((nt2 * 16 * WS_STRIDE + ks * 8) * 4));
                MMA_TF32(acc[nt2 * 2],     a[0], a[1], a[2], a[3], b[0], b[1]);
                MMA_TF32(acc[nt2 * 2 + 1], a[0], a[1], a[2], a[3], b[2], b[3]);
            }
        }
        __syncthreads();
    }

    // epilogue 1
#pragma unroll
    for (int nt = 0; nt < 16; ++nt) {
        int col = nt * 8 + tig * 2;
        float2 v0, v1;
        v0.x = to_tf32(fmaxf(acc[nt][0] + sBias[col], 0.f));
        v0.y = to_tf32(fmaxf(acc[nt][1] + sBias[col + 1], 0.f));
        v1.x = to_tf32(fmaxf(acc[nt][2] + sBias[col], 0.f));
        v1.y = to_tf32(fmaxf(acc[nt][3] + sBias[col + 1], 0.f));
        *(float2*)(hs + r0 * HS_STRIDE + col) = v0;
        *(float2*)(hs + (r0 + 8) * HS_STRIDE + col) = v1;
    }
    __syncthreads();

    // Layers 2 and 3
    for (int l = 0; l < 2; ++l) {
        const float* Wt = l ? g_Wt3 : g_Wt2;
#pragma unroll
        for (int nt = 0; nt < 16; ++nt)
#pragma unroll
            for (int j = 0; j < 4; ++j) acc[nt][j] = 0.f;

        for (int kt = 0; kt < 4; ++kt) {
#pragma unroll
            for (int it = 0; it < 4; ++it) {
                int i = tid + it * 256;
                int n = i >> 3, q = i & 7;
                float4 w = *(const float4*)(Wt + (size_t)n * 128 + kt * 32 + q * 4);
                *(float4*)(ws + n * WS_STRIDE + q * 4) = w;
            }
            __syncthreads();
#pragma unroll
            for (int ks = 0; ks < 4; ++ks) {
                uint32_t a[4];
                ldsm4(a, aH + (uint32_t)((kt * 32 + ks * 8) * 4));
#pragma unroll
                for (int nt2 = 0; nt2 < 8; ++nt2) {
                    uint32_t b[4];
                    ldsm4(b, bW + (uint32_t)((nt2 * 16 * WS_STRIDE + ks * 8) * 4));
                    MMA_TF32(acc[nt2 * 2],     a[0], a[1], a[2], a[3], b[0], b[1]);
                    MMA_TF32(acc[nt2 * 2 + 1], a[0], a[1], a[2], a[3], b[2], b[3]);
                }
            }
            __syncthreads();
        }

        if (l == 0) {
#pragma unroll
            for (int nt = 0; nt < 16; ++nt) {
                int col = nt * 8 + tig * 2;
                float2 v0, v1;
                v0.x = to_tf32(fmaxf(acc[nt][0] + sBias[128 + col], 0.f));
                v0.y = to_tf32(fmaxf(acc[nt][1] + sBias[128 + col + 1], 0.f));
                v1.x = to_tf32(fmaxf(acc[nt][2] + sBias[128 + col], 0.f));
                v1.y = to_tf32(fmaxf(acc[nt][3] + sBias[128 + col + 1], 0.f));
                *(float2*)(hs + r0 * HS_STRIDE + col) = v0;
                *(float2*)(hs + (r0 + 8) * HS_STRIDE + col) = v1;
            }
            __syncthreads();
        }
    }

    // Final: +b3, LayerNorm, gamma/beta, residual
    {
        float s0 = 0.f, sq0 = 0.f, s1 = 0.f, sq1 = 0.f;
#pragma unroll
        for (int nt = 0; nt < 16; ++nt) {
            int col = nt * 8 + tig * 2;
            acc[nt][0] += sBias[256 + col];
            acc[nt][1] += sBias[256 + col + 1];
            acc[nt][2] += sBias[256 + col];
            acc[nt][3] += sBias[256 + col + 1];
            s0 += acc[nt][0] + acc[nt][1];
            sq0 += acc[nt][0] * acc[nt][0] + acc[nt][1] * acc[nt][1];
            s1 += acc[nt][2] + acc[nt][3];
            sq1 += acc[nt][2] * acc[nt][2] + acc[nt][3] * acc[nt][3];
        }
#pragma unroll
        for (int o = 1; o <= 2; o <<= 1) {
            s0 += __shfl_xor_sync(0xFFFFFFFFu, s0, o);
            sq0 += __shfl_xor_sync(0xFFFFFFFFu, sq0, o);
            s1 += __shfl_xor_sync(0xFFFFFFFFu, s1, o);
            sq1 += __shfl_xor_sync(0xFFFFFFFFu, sq1, o);
        }
        float mu0 = s0 * (1.f / 128.f);
        float ri0 = rsqrtf(sq0 * (1.f / 128.f) - mu0 * mu0 + EPS);
        float mu1 = s1 * (1.f / 128.f);
        float ri1 = rsqrtf(sq1 * (1.f / 128.f) - mu1 * mu1 + EPS);

        int node0 = base + r0;
        int node1 = base + r0 + 8;
#pragma unroll
        for (int nt = 0; nt < 16; ++nt) {
            int col = nt * 8 + tig * 2;
            float g0 = sBias[384 + col], g1 = sBias[384 + col + 1];
            float be0 = sBias[512 + col], be1 = sBias[512 + col + 1];
            if (node0 < N_NODE) {
                float2 nv = *(const float2*)(nf + (size_t)node0 * FD + col);
                float2 o;
                o.x = (acc[nt][0] - mu0) * ri0 * g0 + be0 + nv.x;
                o.y = (acc[nt][1] - mu0) * ri0 * g1 + be1 + nv.y;
                *(float2*)(out + (size_t)node0 * FD + col) = o;
            }
            if (node1 < N_NODE) {
                float2 nv = *(const float2*)(nf + (size_t)node1 * FD + col);
                float2 o;
                o.x = (acc[nt][2] - mu1) * ri1 * g0 + be0 + nv.x;
                o.y = (acc[nt][3] - mu1) * ri1 * g1 + be1 + nv.y;
                *(float2*)(out + (size_t)node1 * FD + col) = o;
            }
        }
    }
}

// ---------------------------------------------------------------------------
extern "C" void kernel_launch(void* const* d_in, const int* in_sizes, int n_in,
                              void* d_out, int out_size) {
    const float* node_feature = (const float*)d_in[0];
    const int* edge_matrix    = (const int*)d_in[1];
    const float* edge_feature = (const float*)d_in[2];
    const float* W1 = (const float*)d_in[3];
    const float* b1 = (const float*)d_in[4];
    const float* W2 = (const float*)d_in[5];
    const float* b2 = (const float*)d_in[6];
    const float* W3 = (const float*)d_in[7];
    const float* b3 = (const float*)d_in[8];
    const float* gamma = (const float*)d_in[9];
    const float* beta  = (const float*)d_in[10];
    float* out = (float*)d_out;

    static void* cnt_ptr = nullptr;
    static int inited = 0;
    if (!inited) {
        cudaGetSymbolAddress(&cnt_ptr, g_cnt);
        cudaFuncSetAttribute(mlp_mma_kernel,
                             cudaFuncAttributeMaxDynamicSharedMemorySize, SMEM_BYTES);
        inited = 1;
    }

    // CSR build
    cudaMemsetAsync(cnt_ptr, 0, N_NODE * sizeof(int));
    hist_kernel<<<(N_EDGE + 255) / 256, 256>>>(edge_matrix);
    scan_a_kernel<<<NBLK, 256>>>();
    scan_b_kernel<<<1, 32>>>();
    scan_c_kernel<<<(N_NODE + 255) / 256, 256>>>();
    fill_kernel<<<(N_EDGE + 255) / 256, 256>>>(edge_matrix);

    // weight prep (independent; overlaps nothing but cheap)
    prep_weights_kernel<<<(256 * 128 + 2 * 128 * 128 + 255) / 256, 256>>>(W1, W2, W3);

    // gather (replaces atomic scatter; writes every agg row)
    gather_kernel<<<(N_NODE + 7) / 8, 256>>>(edge_feature);

    // fused MLP + LN + residual
    int grid = (N_NODE + TM - 1) / TM;
    mlp_mma_kernel<<<grid, 256, SMEM_BYTES>>>(node_feature, b1, b2, b3,
                                              gamma, beta, out);
}